// round 1
// baseline (speedup 1.0000x reference)
#include <cuda_runtime.h>

#define B_DIM   256
#define T_DIM   168
#define C_DIM   1024
#define NSEQ    168
#define HORIZON 24

// ---- packed f32x2 helpers (Blackwell sm_103a) ----
__device__ __forceinline__ unsigned long long pack2(float lo, float hi) {
    unsigned long long r;
    asm("mov.b64 %0, {%1, %2};" : "=l"(r) : "f"(lo), "f"(hi));
    return r;
}
__device__ __forceinline__ unsigned long long fma2(unsigned long long a,
                                                   unsigned long long b,
                                                   unsigned long long c) {
    unsigned long long d;
    asm("fma.rn.f32x2 %0, %1, %2, %3;" : "=l"(d) : "l"(a), "l"(b), "l"(c));
    return d;
}
__device__ __forceinline__ unsigned long long add2(unsigned long long a,
                                                   unsigned long long b) {
    unsigned long long d;
    asm("add.rn.f32x2 %0, %1, %2;" : "=l"(d) : "l"(a), "l"(b));
    return d;
}

// One thread = one pair of adjacent channels (c0, c0+1).
// Block = 128 threads = 256 channels. Grid = (C/256, B).
__global__ __launch_bounds__(128)
void ar_forecast_kernel(const float* __restrict__ y,
                        const float* __restrict__ w,
                        const float* __restrict__ bias,
                        float* __restrict__ out) {
    __shared__ unsigned long long sh_w[NSEQ];   // (w[i], w[i]) duplicated pairs

    const int tid = threadIdx.x;
    for (int i = tid; i < NSEQ; i += 128) {
        float wv = w[i];
        sh_w[i] = pack2(wv, wv);
    }
    __syncthreads();

    const int b  = blockIdx.y;
    const int c0 = blockIdx.x * 256 + tid * 2;

    const float* yp = y + ((long long)b * T_DIM) * C_DIM + c0;

    unsigned long long acc[HORIZON];
#pragma unroll
    for (int h = 0; h < HORIZON; ++h) acc[h] = 0ull;  // packed (0.0f, 0.0f)

    // ---- triangular prologue: t = 0..23, only h <= t contribute ----
#pragma unroll
    for (int t = 0; t < HORIZON; ++t) {
        unsigned long long y2 =
            *reinterpret_cast<const unsigned long long*>(yp + (long long)t * C_DIM);
#pragma unroll
        for (int h = 0; h <= t; ++h)
            acc[h] = fma2(y2, sh_w[t - h], acc[h]);
    }

    // ---- register ring buffer for the sliding w window ----
    // invariant: wreg[i % 24] holds w[i] for the last 24 loaded indices
    unsigned long long wreg[HORIZON];
#pragma unroll
    for (int i = 0; i < HORIZON; ++i) wreg[i] = sh_w[i];

    // ---- main loop: t = 24..167, full 24-FMA window per t ----
#pragma unroll 1
    for (int tb = HORIZON; tb < T_DIM; tb += HORIZON) {
        const float* ypb = yp + (long long)tb * C_DIM;
#pragma unroll
        for (int k = 0; k < HORIZON; ++k) {
            wreg[k] = sh_w[tb + k];   // slot (tb+k) % 24 == k
            unsigned long long y2 =
                *reinterpret_cast<const unsigned long long*>(ypb + (long long)k * C_DIM);
#pragma unroll
            for (int h = 0; h < HORIZON; ++h) {
                const int slot = ((k - h) % HORIZON + HORIZON) % HORIZON; // compile-time
                acc[h] = fma2(y2, wreg[slot], acc[h]);
            }
        }
    }

    // ---- AR recursion on the 24 predictions ----
    const float bvf = bias[0];
    const unsigned long long b2 = pack2(bvf, bvf);

    unsigned long long pred[HORIZON];
#pragma unroll
    for (int h = 0; h < HORIZON; ++h) {
        unsigned long long p = add2(acc[h], b2);
#pragma unroll
        for (int j = 0; j < h; ++j)
            p = fma2(sh_w[NSEQ - h + j], pred[j], p);
        pred[h] = p;
    }

    // ---- store out[b, h, c] ----
    float* op = out + ((long long)b * HORIZON) * C_DIM + c0;
#pragma unroll
    for (int h = 0; h < HORIZON; ++h)
        *reinterpret_cast<unsigned long long*>(op + (long long)h * C_DIM) = pred[h];
}

extern "C" void kernel_launch(void* const* d_in, const int* in_sizes, int n_in,
                              void* d_out, int out_size) {
    // metadata order: x (unused), y, w, b
    const float* y    = (const float*)d_in[1];
    const float* w    = (const float*)d_in[2];
    const float* bias = (const float*)d_in[3];
    float* out        = (float*)d_out;

    dim3 grid(C_DIM / 256, B_DIM);
    ar_forecast_kernel<<<grid, 128>>>(y, w, bias, out);
}

// round 2
// speedup vs baseline: 1.0936x; 1.0936x over previous
#include <cuda_runtime.h>
#include <cstdint>

#define B_DIM   256
#define T_DIM   168
#define C_DIM   1024
#define NSEQ    168
#define HORIZON 24

#define STAGES      3
#define T_STAGE     24                    // timesteps per stage
#define GROUPS      (T_DIM / T_STAGE)     // 7
#define STAGE_U64   (T_STAGE * 128)       // 3072 u64 per stage (24 rows x 128 pairs)
#define STAGE_BYTES (STAGE_U64 * 8)       // 24576
#define WOFF_U64    (STAGES * STAGE_U64)  // 9216
#define SMEM_BYTES  (WOFF_U64 * 8 + NSEQ * 8)   // 75072

// ---- packed f32x2 helpers (Blackwell sm_103a) ----
__device__ __forceinline__ unsigned long long pack2(float lo, float hi) {
    unsigned long long r;
    asm("mov.b64 %0, {%1, %2};" : "=l"(r) : "f"(lo), "f"(hi));
    return r;
}
__device__ __forceinline__ unsigned long long fma2(unsigned long long a,
                                                   unsigned long long b,
                                                   unsigned long long c) {
    unsigned long long d;
    asm("fma.rn.f32x2 %0, %1, %2, %3;" : "=l"(d) : "l"(a), "l"(b), "l"(c));
    return d;
}
__device__ __forceinline__ unsigned long long add2(unsigned long long a,
                                                   unsigned long long b) {
    unsigned long long d;
    asm("add.rn.f32x2 %0, %1, %2;" : "=l"(d) : "l"(a), "l"(b));
    return d;
}
__device__ __forceinline__ void cp16(uint32_t saddr, const void* gptr) {
    asm volatile("cp.async.cg.shared.global [%0], [%1], 16;"
                 :: "r"(saddr), "l"(gptr));
}
__device__ __forceinline__ void cp_commit() {
    asm volatile("cp.async.commit_group;");
}
template<int N>
__device__ __forceinline__ void cp_wait() {
    asm volatile("cp.async.wait_group %0;" :: "n"(N));
}

// One thread = one pair of adjacent channels. Block = 128 threads = 256 channels.
// Grid = (C/256, B).
__global__ __launch_bounds__(128)
void ar_forecast_kernel(const float* __restrict__ y,
                        const float* __restrict__ w,
                        const float* __restrict__ bias,
                        float* __restrict__ out) {
    extern __shared__ unsigned long long sm[];
    const int tid = threadIdx.x;
    const int b   = blockIdx.y;
    const int c0  = blockIdx.x * 256 + tid * 2;

    const uint32_t sbase =
        (uint32_t)__cvta_generic_to_shared((void*)sm);

    // y rows for this block: 1024 contiguous bytes at stride 4096
    const char* ybase = (const char*)(y + ((long long)b * T_DIM) * C_DIM
                                        + blockIdx.x * 256);

    // ---- stage prefetch: 24 rows x 1024 B, 12 x 16B chunks per thread ----
    auto prefetch = [&](int s, int g) {
        const uint32_t sdst = sbase + s * STAGE_BYTES;
        const char*    gsrc = ybase + (long long)g * T_STAGE * 4096;
#pragma unroll
        for (int j = 0; j < 12; ++j) {
            int id  = j * 128 + tid;
            int row = id >> 6;              // 0..23
            int col = (id & 63) << 4;       // byte column 0..1008
            cp16(sdst + row * 1024 + col, gsrc + (long long)row * 4096 + col);
        }
    };

    // kick off stages 0 and 1
    prefetch(0, 0); cp_commit();
    prefetch(1, 1); cp_commit();

    // w duplicated-pair table in smem (regular stores, covered by first sync)
    for (int i = tid; i < NSEQ; i += 128) {
        float wv = w[i];
        sm[WOFF_U64 + i] = pack2(wv, wv);
    }

    unsigned long long acc[HORIZON];
#pragma unroll
    for (int h = 0; h < HORIZON; ++h) acc[h] = 0ull;

    unsigned long long wreg[HORIZON];

    // ================= group 0: triangular prologue =================
    cp_wait<1>();
    __syncthreads();
    prefetch(2, 2); cp_commit();
    {
        const unsigned long long* st = sm;            // stage 0
#pragma unroll
        for (int t = 0; t < T_STAGE; ++t) {
            unsigned long long y2 = st[t * 128 + tid];
#pragma unroll
            for (int h = 0; h <= t; ++h)
                acc[h] = fma2(y2, sm[WOFF_U64 + (t - h)], acc[h]);
        }
    }
#pragma unroll
    for (int i = 0; i < HORIZON; ++i) wreg[i] = sm[WOFF_U64 + i];

    // ================= groups 1..6: uniform 24-wide windows =================
#pragma unroll 1
    for (int g = 1; g < GROUPS; ++g) {
        if (g < GROUPS - 1) { cp_wait<1>(); } else { cp_wait<0>(); }
        __syncthreads();
        if (g + 2 < GROUPS) { prefetch((g + 2) % STAGES, g + 2); cp_commit(); }

        const unsigned long long* st = sm + (g % STAGES) * STAGE_U64;
        const int tb = g * T_STAGE;
#pragma unroll
        for (int k = 0; k < T_STAGE; ++k) {
            wreg[k] = sm[WOFF_U64 + tb + k];          // slot (tb+k)%24 == k
            unsigned long long y2 = st[k * 128 + tid];
#pragma unroll
            for (int h = 0; h < HORIZON; ++h) {
                const int slot = ((k - h) % HORIZON + HORIZON) % HORIZON;
                acc[h] = fma2(y2, wreg[slot], acc[h]);
            }
        }
    }

    // ================= AR recursion over the 24 predictions =================
    const float bvf = bias[0];
    const unsigned long long b2 = pack2(bvf, bvf);

    unsigned long long pred[HORIZON];
#pragma unroll
    for (int h = 0; h < HORIZON; ++h) {
        unsigned long long p = add2(acc[h], b2);
#pragma unroll
        for (int j = 0; j < h; ++j)
            p = fma2(sm[WOFF_U64 + (NSEQ - h + j)], pred[j], p);
        pred[h] = p;
    }

    // ---- store out[b, h, c] ----
    float* op = out + ((long long)b * HORIZON) * C_DIM + c0;
#pragma unroll
    for (int h = 0; h < HORIZON; ++h)
        *reinterpret_cast<unsigned long long*>(op + (long long)h * C_DIM) = pred[h];
}

extern "C" void kernel_launch(void* const* d_in, const int* in_sizes, int n_in,
                              void* d_out, int out_size) {
    // metadata order: x (unused), y, w, b
    const float* y    = (const float*)d_in[1];
    const float* w    = (const float*)d_in[2];
    const float* bias = (const float*)d_in[3];
    float* out        = (float*)d_out;

    static bool attr_set = false;
    if (!attr_set) {
        cudaFuncSetAttribute(ar_forecast_kernel,
                             cudaFuncAttributeMaxDynamicSharedMemorySize,
                             SMEM_BYTES);
        attr_set = true;
    }

    dim3 grid(C_DIM / 256, B_DIM);
    ar_forecast_kernel<<<grid, 128, SMEM_BYTES>>>(y, w, bias, out);
}